// round 14
// baseline (speedup 1.0000x reference)
#include <cuda_runtime.h>

#define NW 10
typedef unsigned long long u64;

// Precomputed per-pass diag tables: entry = ((c,c),(-s,s)) as two packed f32x2
__device__ ulonglong2 g_tab[8][1024];
__device__ float2 g_ry[8][NW];      // RY half-angle (cos,sin) per pass/wire
__device__ float2 g_init;           // |0> phase with block-0 rz(p0) folded

// ---------- packed (re,im) f32x2 helpers ----------
__device__ __forceinline__ u64 pk2(float x, float y) {
    u64 r; asm("mov.b64 %0, {%1,%2};" : "=l"(r) : "f"(x), "f"(y)); return r;
}
__device__ __forceinline__ void upk2(u64 v, float &x, float &y) {
    asm("mov.b64 {%0,%1}, %2;" : "=f"(x), "=f"(y) : "l"(v));
}
__device__ __forceinline__ u64 pfma(u64 a, u64 b, u64 c) {
    u64 d; asm("fma.rn.f32x2 %0, %1, %2, %3;" : "=l"(d) : "l"(a), "l"(b), "l"(c)); return d;
}
__device__ __forceinline__ u64 pmul(u64 a, u64 b) {
    u64 d; asm("mul.rn.f32x2 %0, %1, %2;" : "=l"(d) : "l"(a), "l"(b)); return d;
}
__device__ __forceinline__ u64 dup2(float v) { return pk2(v, v); }

__host__ __device__ constexpr int grayC(int x) { return x ^ (x >> 1); }

// host-side packers for precompute
__device__ __forceinline__ u64 pk2d(float x, float y) { return pk2(x, y); }

// ---------- table precompute: 64 blocks x 128 threads ----------
__global__ void precompute_tables(const float* __restrict__ params) {
    int p = blockIdx.x >> 3;                         // 0..7  (pass)
    int s = ((blockIdx.x & 7) << 7) | threadIdx.x;   // 0..1023
    int k = p >> 1, ry = p & 1;

    int idx = s;                 // reference perm chain
    for (int q = 9; q >= 0; --q) {
        int c = q, t = (q + 1) % NW;
        int bit = (idx >> (9 - c)) & 1;
        idx ^= bit << (9 - t);
    }

    const float* thA = params + (k * 6 + (ry ? 5 : 2)) * NW;
    float ang = 0.f;
#pragma unroll
    for (int w = 0; w < NW; w++)
        ang += thA[w] * ((float)((idx >> (9 - w)) & 1) - 0.5f);
    if (ry == 0) {
        const float* th3 = params + (k * 6 + 3) * NW;
#pragma unroll
        for (int w = 0; w < NW; w++)
            ang += th3[w] * ((float)((s >> (9 - w)) & 1) - 0.5f);
    } else if (k < 3) {
        const float* th0 = params + ((k + 1) * 6) * NW;
#pragma unroll
        for (int w = 0; w < NW; w++)
            ang += th0[w] * ((float)((s >> (9 - w)) & 1) - 0.5f);
    }
    float sn, cn; sincosf(ang, &sn, &cn);
    ulonglong2 e;
    e.x = pk2d(cn, cn);
    e.y = pk2d(-sn, sn);
    g_tab[p][s] = e;

    if (blockIdx.x == 0) {
        int t = threadIdx.x;
        if (t < 80) {
            int pp = t / 10, w = t % 10;
            int kk = pp >> 1, rr = pp & 1;
            float th = 0.5f * params[(kk * 6 + (rr ? 4 : 1)) * NW + w];
            g_ry[pp][w] = make_float2(cosf(th), sinf(th));
        }
        if (t == 80) {
            float a = 0.f;
#pragma unroll
            for (int w = 0; w < NW; w++) a -= 0.5f * params[w];
            float sn2, cn2; sincosf(a, &sn2, &cn2);
            g_init = make_float2(cn2, sn2);
        }
    }
}

// ---------- main kernel: 1 warp per batch element, no smem, no barriers ----------
// state s = (j<<5) | lane :
//   lane bits 0..4 = state bits 0..4  -> wires 9..5 (shfl butterflies)
//   reg  bits 0..4 = state bits 5..9  -> wires 4..0 (register butterflies)
__global__ __launch_bounds__(32, 20)
void quantum_shfl_kernel(const float* __restrict__ x,
                         float* __restrict__ out)
{
    const int lane = threadIdx.x;
    const int b    = blockIdx.x;
    const unsigned FULL = 0xFFFFFFFFu;

    // encoding precomputes
    float xlane = 0.f;
#pragma unroll
    for (int w = 5; w < NW; w++)
        xlane += x[b * NW + w] * ((float)((lane >> (9 - w)) & 1) - 0.5f);
    float h[5];
#pragma unroll
    for (int w = 0; w < 5; w++) h[w] = 0.5f * x[b * NW + w];
    const float hx0 = 2.f * h[0];   // = x[b][0]

    // perm-shfl per-thread constants
    const int U   = (lane ^ (lane >> 1)) & 31;    // source-lane base
    const int par = __popc(lane) & 1;             // reader-parity bit

    // ---- pass-0 sparse init: RY layer applied to |0> is a product state ----
    // amp(s) = init_phase * prod_w (bit_w(s) ? sin_w : cos_w)
    u64 st[32];
    {
        float2 gi = g_init;
        float laneF = 1.f;
#pragma unroll
        for (int w = 5; w < 10; w++) {
            float2 c = g_ry[0][w];
            laneF *= ((lane >> (9 - w)) & 1) ? c.y : c.x;
        }
        u64 giP = pk2(gi.x * laneF, gi.y * laneF);
        float2 c0 = g_ry[0][0], c1 = g_ry[0][1], c2 = g_ry[0][2],
               c3 = g_ry[0][3], c4 = g_ry[0][4];
#pragma unroll
        for (int j = 0; j < 32; j++) {
            float f = ((j & 16) ? c0.y : c0.x)
                    * ((j & 8)  ? c1.y : c1.x)
                    * ((j & 4)  ? c2.y : c2.x)
                    * ((j & 2)  ? c3.y : c3.x)
                    * ((j & 1)  ? c4.y : c4.x);
            st[j] = pmul(dup2(f), giP);
        }
    }

    // ============================ circuit: 8 half-block passes ============================
#pragma unroll 1
    for (int pass = 0; pass < 8; ++pass) {

        if (pass != 0) {
            // ---- RY register wires 0..4 (reg bit 4-w) ----
#pragma unroll
            for (int w = 0; w < 5; w++) {
                float2 c = g_ry[pass][w];
                u64 c2 = dup2(c.x), s2 = dup2(c.y), ns2 = dup2(-c.y);
                const int m = 1 << (4 - w);
#pragma unroll
                for (int j = 0; j < 32; j++) {
                    if (!(j & m)) {
                        u64 a0 = st[j], a1 = st[j | m];
                        st[j]     = pfma(c2, a0, pmul(ns2, a1));
                        st[j | m] = pfma(s2, a0, pmul(c2, a1));
                    }
                }
            }

            // ---- RY lane wires 5..9 (lane bit 9-w, shfl butterflies) ----
#pragma unroll
            for (int w = 5; w < 10; w++) {
                float2 c = g_ry[pass][w];
                u64 c2   = dup2(c.x);
                u64 coef = ((lane >> (9 - w)) & 1) ? dup2(c.y) : dup2(-c.y);
                const int mm = 1 << (9 - w);
#pragma unroll
                for (int j = 0; j < 32; j++) {
                    u64 pv = __shfl_xor_sync(FULL, st[j], mm);
                    st[j] = pfma(c2, st[j], pmul(coef, pv));
                }
            }
        }

        // ---- perm via shfl.idx, fused with packed diag (+enc) ----
        const ulonglong2* __restrict__ tab = g_tab[pass];
        const bool doEnc = (pass & 1) && (pass < 7);   // passes 1,3,5

#pragma unroll
        for (int jj = 0; jj < 16; jj++) {
            const int gsl     = grayC(jj);              // frees {gsl, gsl^24}
            const int srcLane = U ^ ((jj & 1) << 4);
            const bool sel    = (par ^ (jj & 1)) != 0;

            u64 a  = st[gsl];
            u64 bb = st[gsl ^ 24];
            u64 v0 = __shfl_sync(FULL, sel ? bb : a, srcLane);   // logical jj
            u64 v1 = __shfl_sync(FULL, sel ? a : bb, srcLane);   // logical jj|16

            // packed diag rotation: out = (c,c)*v + (-s,s)*swap(v)
            float o0x, o0y; upk2(v0, o0x, o0y);
            ulonglong2 t0 = tab[(jj << 5) | lane];
            u64 r0p = pfma(t0.x, v0, pmul(t0.y, pk2(o0y, o0x)));

            float o1x, o1y; upk2(v1, o1x, o1y);
            ulonglong2 t1 = tab[((jj | 16) << 5) | lane];
            u64 r1p = pfma(t1.x, v1, pmul(t1.y, pk2(o1y, o1x)));

            if (doEnc) {
                float ang0 = xlane - h[0]
                    + ((jj & 8) ? h[1] : -h[1]) + ((jj & 4) ? h[2] : -h[2])
                    + ((jj & 2) ? h[3] : -h[3]) + ((jj & 1) ? h[4] : -h[4]);
                float ang1 = ang0 + hx0;
                float se0, ce0, se1, ce1;
                __sincosf(ang0, &se0, &ce0);
                __sincosf(ang1, &se1, &ce1);
                float r0, i0; upk2(r0p, r0, i0);
                float r1, i1; upk2(r1p, r1, i1);
                st[gsl]      = pk2(r0 * ce0 - i0 * se0, r0 * se0 + i0 * ce0);
                st[gsl ^ 24] = pk2(r1 * ce1 - i1 * se1, r1 * se1 + i1 * ce1);
            } else {
                st[gsl]      = r0p;
                st[gsl ^ 24] = r1p;
            }
        }

        // ---- renormalize: physical gray(j) holds logical j -> x[p] <- x[gray(p)] ----
        {
            u64 tmp;
            tmp = st[2];  st[2]  = st[3];  st[3]  = tmp;                                     // (2 3)
            tmp = st[4];  st[4]  = st[6];  st[6]  = st[5];  st[5]  = st[7];  st[7]  = tmp;   // (4 6 5 7)
            tmp = st[8];  st[8]  = st[12]; st[12] = st[10]; st[10] = st[15]; st[15] = tmp;   // (8 12 10 15)
            tmp = st[9];  st[9]  = st[13]; st[13] = st[11]; st[11] = st[14]; st[14] = tmp;   // (9 13 11 14)
            tmp = st[16]; st[16] = st[24]; st[24] = st[20]; st[20] = st[30]; st[30] = st[17];
            st[17] = st[25]; st[25] = st[21]; st[21] = st[31]; st[31] = tmp;                 // (16 24 20 30 17 25 21 31)
            tmp = st[18]; st[18] = st[27]; st[27] = st[22]; st[22] = st[29]; st[29] = st[19];
            st[19] = st[26]; st[26] = st[23]; st[23] = st[28]; st[28] = tmp;                 // (18 27 22 29 19 26 23 28)
        }
    }

    // ============================ measurement ============================
    float aj[5] = {0.f, 0.f, 0.f, 0.f, 0.f};   // wires 0..4: sign from bit (4-w) of j
    float pt = 0.f;
#pragma unroll
    for (int j = 0; j < 32; j++) {
        float re, im; upk2(st[j], re, im);
        float pr = fmaf(re, re, im * im);
        pt += pr;
        aj[0] += (j & 16) ? -pr : pr;
        aj[1] += (j & 8)  ? -pr : pr;
        aj[2] += (j & 4)  ? -pr : pr;
        aj[3] += (j & 2)  ? -pr : pr;
        aj[4] += (j & 1)  ? -pr : pr;
    }
    float acc[NW];
#pragma unroll
    for (int w = 0; w < 5; w++) acc[w] = aj[w];
#pragma unroll
    for (int w = 5; w < NW; w++)
        acc[w] = ((lane >> (9 - w)) & 1) ? -pt : pt;

#pragma unroll
    for (int off = 16; off > 0; off >>= 1) {
#pragma unroll
        for (int w = 0; w < NW; w++)
            acc[w] += __shfl_xor_sync(FULL, acc[w], off);
    }
    if (lane == 0) {
#pragma unroll
        for (int w = 0; w < NW; w++) out[b * NW + w] = acc[w];
    }
}

extern "C" void kernel_launch(void* const* d_in, const int* in_sizes, int n_in,
                              void* d_out, int out_size)
{
    const float* x      = (const float*)d_in[0];   // (2048, 10)
    const float* params = (const float*)d_in[1];   // (4, 6, 10)
    float* out          = (float*)d_out;           // (1, 2048, 10)
    precompute_tables<<<64, 128>>>(params);
    quantum_shfl_kernel<<<2048, 32>>>(x, out);
}